// round 8
// baseline (speedup 1.0000x reference)
#include <cuda_runtime.h>

#define NUM_C  8192
#define NUM_B  256
#define EPSF   1e-6f

// ---- kernel A (label scan) geometry ----
#define SPLITA 4
#define CHA    (NUM_C / SPLITA)      // 2048
#define NTA    256

// ---- kernel B (denom) geometry ----
#define SPLITB 2
#define CHB    (NUM_C / SPLITB)      // 4096
#define NTB    256
#define NWARPB (NTB / 32)

// cross-kernel/cross-block state (allocation-free rule: __device__ globals;
// g_denom/g_row_cnt/g_sum/g_cnt are drained+reset in-kernel each replay;
// g_label is unconditionally overwritten by kernel A before kernel B reads it)
__device__ int          g_label[NUM_B];
__device__ float        g_denom[NUM_B];
__device__ unsigned int g_row_cnt[NUM_B];
__device__ float        g_sum = 0.0f;
__device__ unsigned int g_cnt = 0u;

// ============ kernel A: find the one-hot label per row ============
__global__ __launch_bounds__(NTA)
void seesaw_labels_kernel(const float* __restrict__ targets)
{
    const int chunk = blockIdx.x;            // 0..SPLITA-1
    const int b     = blockIdx.y;            // row
    const int tid   = threadIdx.x;

    const int4* tg4 = (const int4*)(targets + (size_t)b * NUM_C
                                            + (size_t)chunk * CHA);
    // 2 batched int4 loads per thread (2048 elems / 4 / 256)
    int4 t0 = tg4[tid + 0 * NTA];
    int4 t1 = tg4[tid + 1 * NTA];

    int l = -1;
    if (t0.x | t0.y | t0.z | t0.w) {
        int j = chunk * CHA + (tid + 0 * NTA) * 4;
        l = t0.x ? j : (t0.y ? j + 1 : (t0.z ? j + 2 : j + 3));
    }
    if (t1.x | t1.y | t1.z | t1.w) {
        int j = chunk * CHA + (tid + 1 * NTA) * 4;
        l = t1.x ? j : (t1.y ? j + 1 : (t1.z ? j + 2 : j + 3));
    }
    if (l >= 0) g_label[b] = l;              // exactly one thread grid-wide per row
}

// ============ kernel B: denom partial dots + loss + mean ============
__global__ __launch_bounds__(NTB)
void seesaw_denom_kernel(const float* __restrict__ logits,
                         const float* __restrict__ s,
                         float* __restrict__ out)
{
    __shared__ float sh_warp[NWARPB];

    const int chunk = blockIdx.x;            // 0..SPLITB-1
    const int b     = blockIdx.y;            // row
    const int tid   = threadIdx.x;
    const int lane  = tid & 31;
    const int wid   = tid >> 5;

    const size_t rowoff = (size_t)b * NUM_C;
    const int lab = g_label[b];              // 4 bytes, L2-hot, no scan

    const float4* lg4 = (const float4*)(logits + rowoff + (size_t)chunk * CHB);
    const float4* s4  = (const float4*)(s + (size_t)lab * NUM_C
                                          + (size_t)chunk * CHB);

    // 8 independent 128B loads in flight per thread before any math
    float4 l0 = lg4[tid + 0 * NTB];
    float4 l1 = lg4[tid + 1 * NTB];
    float4 l2 = lg4[tid + 2 * NTB];
    float4 l3 = lg4[tid + 3 * NTB];
    float4 s0 = s4[tid + 0 * NTB];
    float4 s1 = s4[tid + 1 * NTB];
    float4 s2 = s4[tid + 2 * NTB];
    float4 s3 = s4[tid + 3 * NTB];

    // partial denom: sum_j s[lab,j]*exp(logits[b,j])  (s diag==1 folds the
    // +expl term; max-shift dropped: only rescales +eps by e^{-max}, ~1e-8)
    float acc = 0.f;
    acc += s0.x * __expf(l0.x) + s0.y * __expf(l0.y)
         + s0.z * __expf(l0.z) + s0.w * __expf(l0.w);
    acc += s1.x * __expf(l1.x) + s1.y * __expf(l1.y)
         + s1.z * __expf(l1.z) + s1.w * __expf(l1.w);
    acc += s2.x * __expf(l2.x) + s2.y * __expf(l2.y)
         + s2.z * __expf(l2.z) + s2.w * __expf(l2.w);
    acc += s3.x * __expf(l3.x) + s3.y * __expf(l3.y)
         + s3.z * __expf(l3.z) + s3.w * __expf(l3.w);

    // block reduce
    #pragma unroll
    for (int off = 16; off > 0; off >>= 1)
        acc += __shfl_down_sync(0xffffffffu, acc, off);
    if (lane == 0) sh_warp[wid] = acc;
    __syncthreads();

    if (tid == 0) {
        float blk = sh_warp[0];
        #pragma unroll
        for (int w = 1; w < NWARPB; w++) blk += sh_warp[w];

        atomicAdd(&g_denom[b], blk);
        __threadfence();
        unsigned int tkt = atomicAdd(&g_row_cnt[b], 1u);
        if (tkt == SPLITB - 1u) {
            // row complete: drain + reset row state for the next graph replay
            float denom = atomicExch(&g_denom[b], 0.0f);
            g_row_cnt[b] = 0u;
            float elab  = __expf(__ldg(logits + rowoff + lab));   // L2-hot
            float sigma = elab / (denom + EPSF);
            float loss  = -logf(sigma + EPSF);

            atomicAdd(&g_sum, loss);
            __threadfence();
            unsigned int t2 = atomicAdd(&g_cnt, 1u);
            if (t2 == NUM_B - 1u) {
                float total = atomicExch(&g_sum, 0.0f);
                g_cnt = 0u;
                out[0] = total * (1.0f / NUM_B);
            }
        }
    }
}

extern "C" void kernel_launch(void* const* d_in, const int* in_sizes, int n_in,
                              void* d_out, int out_size)
{
    const float* logits  = (const float*)d_in[0];
    const float* targets = (const float*)d_in[1];
    const float* s       = (const float*)d_in[2];
    float* out = (float*)d_out;

    dim3 gridA(SPLITA, NUM_B);
    seesaw_labels_kernel<<<gridA, NTA>>>(targets);

    dim3 gridB(SPLITB, NUM_B);
    seesaw_denom_kernel<<<gridB, NTB>>>(logits, s, out);
}

// round 10
// speedup vs baseline: 1.4163x; 1.4163x over previous
#include <cuda_runtime.h>

#define NUM_C 8192
#define NUM_B 256
#define NT    512
#define NWARP (NT / 32)
#define EPSF  1e-6f

// cross-block accumulators (allocation-free rule: __device__ globals; reset
// in-kernel after the grid completes so every graph replay starts clean)
__device__ float        g_sum = 0.0f;
__device__ unsigned int g_cnt = 0u;

__global__ __launch_bounds__(NT, 2)   // reg budget 64 -> loads can truly batch
void seesaw_v9_kernel(const float* __restrict__ logits,
                      const float* __restrict__ targets,
                      const float* __restrict__ s,
                      float* __restrict__ out)
{
    __shared__ float sh_warp[NWARP];
    __shared__ int   sh_label;
    __shared__ float sh_elab;

    const int b    = blockIdx.x;
    const int tid  = threadIdx.x;
    const int lane = tid & 31;
    const int wid  = tid >> 5;
    const size_t rowoff = (size_t)b * NUM_C;

    // ---- phase T: targets-only scan (sole label dependency), 4 batched int4 ----
    {
        const int4* tg4 = (const int4*)(targets + rowoff);
        int4 t0 = tg4[tid + 0 * NT];
        int4 t1 = tg4[tid + 1 * NT];
        int4 t2 = tg4[tid + 2 * NT];
        int4 t3 = tg4[tid + 3 * NT];
        int l = -1;
        if (t0.x | t0.y | t0.z | t0.w) {
            int j = (tid + 0 * NT) * 4;
            l = t0.x ? j : (t0.y ? j + 1 : (t0.z ? j + 2 : j + 3));
        }
        if (t1.x | t1.y | t1.z | t1.w) {
            int j = (tid + 1 * NT) * 4;
            l = t1.x ? j : (t1.y ? j + 1 : (t1.z ? j + 2 : j + 3));
        }
        if (t2.x | t2.y | t2.z | t2.w) {
            int j = (tid + 2 * NT) * 4;
            l = t2.x ? j : (t2.y ? j + 1 : (t2.z ? j + 2 : j + 3));
        }
        if (t3.x | t3.y | t3.z | t3.w) {
            int j = (tid + 3 * NT) * 4;
            l = t3.x ? j : (t3.y ? j + 1 : (t3.z ? j + 2 : j + 3));
        }
        if (l >= 0) sh_label = l;          // exactly one thread writes
    }
    __syncthreads();
    const int lab = sh_label;

    // ---- phase S: denom = sum_j s[lab,j]*exp(logits[b,j]); 8 batched float4.
    //      (s diag==1 folds the +expl term; max-shift dropped: it only
    //       rescales +eps by e^{-max}, ~1e-8 relative effect on sigma) ----
    const float4* lg4 = (const float4*)(logits + rowoff);
    const float4* s4  = (const float4*)(s + (size_t)lab * NUM_C);

    float4 l0 = lg4[tid + 0 * NT];
    float4 l1 = lg4[tid + 1 * NT];
    float4 l2 = lg4[tid + 2 * NT];
    float4 l3 = lg4[tid + 3 * NT];
    float4 s0 = s4[tid + 0 * NT];
    float4 s1 = s4[tid + 1 * NT];
    float4 s2 = s4[tid + 2 * NT];
    float4 s3 = s4[tid + 3 * NT];

    float e00 = __expf(l0.x), e01 = __expf(l0.y), e02 = __expf(l0.z), e03 = __expf(l0.w);
    float e10 = __expf(l1.x), e11 = __expf(l1.y), e12 = __expf(l1.z), e13 = __expf(l1.w);
    float e20 = __expf(l2.x), e21 = __expf(l2.y), e22 = __expf(l2.z), e23 = __expf(l2.w);
    float e30 = __expf(l3.x), e31 = __expf(l3.y), e32 = __expf(l3.z), e33 = __expf(l3.w);

    // capture e_lab from registers (kills the tail __ldg+exp dependency)
    {
        const int slot = (lab >> 2) - tid;   // k*NT if this thread owns lab's float4
        const int sub  = lab & 3;
        if (slot == 0 * NT) sh_elab = sub == 0 ? e00 : sub == 1 ? e01 : sub == 2 ? e02 : e03;
        if (slot == 1 * NT) sh_elab = sub == 0 ? e10 : sub == 1 ? e11 : sub == 2 ? e12 : e13;
        if (slot == 2 * NT) sh_elab = sub == 0 ? e20 : sub == 1 ? e21 : sub == 2 ? e22 : e23;
        if (slot == 3 * NT) sh_elab = sub == 0 ? e30 : sub == 1 ? e31 : sub == 2 ? e32 : e33;
    }

    float acc = 0.f;
    acc += s0.x * e00 + s0.y * e01 + s0.z * e02 + s0.w * e03;
    acc += s1.x * e10 + s1.y * e11 + s1.z * e12 + s1.w * e13;
    acc += s2.x * e20 + s2.y * e21 + s2.z * e22 + s2.w * e23;
    acc += s3.x * e30 + s3.y * e31 + s3.z * e32 + s3.w * e33;

    // ---- block reduce ----
    #pragma unroll
    for (int off = 16; off > 0; off >>= 1)
        acc += __shfl_down_sync(0xffffffffu, acc, off);
    if (lane == 0) sh_warp[wid] = acc;
    __syncthreads();

    if (wid == 0) {
        float v = (lane < NWARP) ? sh_warp[lane] : 0.f;
        #pragma unroll
        for (int off = 8; off > 0; off >>= 1)
            v += __shfl_down_sync(0xffffffffu, v, off);

        if (lane == 0) {
            float sigma = sh_elab / (v + EPSF);
            float loss  = -__logf(sigma + EPSF);

            atomicAdd(&g_sum, loss);
            __threadfence();
            unsigned int tkt = atomicAdd(&g_cnt, 1u);
            if (tkt == NUM_B - 1u) {
                float total = atomicExch(&g_sum, 0.0f);   // drain + reset
                g_cnt = 0u;
                out[0] = total * (1.0f / NUM_B);
            }
        }
    }
}

extern "C" void kernel_launch(void* const* d_in, const int* in_sizes, int n_in,
                              void* d_out, int out_size)
{
    const float* logits  = (const float*)d_in[0];
    const float* targets = (const float*)d_in[1];
    const float* s       = (const float*)d_in[2];
    float* out = (float*)d_out;

    seesaw_v9_kernel<<<NUM_B, NT>>>(logits, targets, s, out);
}